// round 1
// baseline (speedup 1.0000x reference)
#include <cuda_runtime.h>
#include <cuda_bf16.h>

// Problem constants
#define Nn   512
#define NN   (Nn * Nn)          // 262144
#define BATCH 64
#define DEG   8

// Ping-pong scratch for the Horner iterate S (B, 2, N, N) = 134 MB each.
// Static __device__ arrays: allowed scratch (no cudaMalloc anywhere).
__device__ float g_buf0[(size_t)BATCH * 2 * NN];
__device__ float g_buf1[(size_t)BATCH * 2 * NN];

// ---------------------------------------------------------------------------
// Fused complex GEMM + add:
//   Dr(b) = C_r + A_r(b) @ X_r(b) - A_i(b) @ X_i(b)
//   Di(b) = C_i + A_r(b) @ X_i(b) + A_i(b) @ X_r(b)
// A batch stride is parametric so the first Horner step can read the
// broadcast coefficient C_7 directly (aStride = 0).
//
// Tiling: BM=BN=64, BK=16, 256 threads, each thread owns a 4x4 micro-tile
// for BOTH real and imag accumulators (shared operand loads => 2x intensity).
// ---------------------------------------------------------------------------
#define BM 64
#define BN 64
#define BK 16

__global__ __launch_bounds__(256, 3) void cgemm_horner_kernel(
    const float* __restrict__ A, long aStride,
    const float* __restrict__ X,
    const float* __restrict__ C,
    float* __restrict__ D)
{
    __shared__ float As_r[BK][BM + 4];   // A stored transposed: As[k][m]
    __shared__ float As_i[BK][BM + 4];
    __shared__ float Bs_r[BK][BN];       // B stored straight:   Bs[k][n]
    __shared__ float Bs_i[BK][BN];

    const int b  = blockIdx.z;
    const int bm = blockIdx.y * BM;
    const int bn = blockIdx.x * BN;
    const int tid = threadIdx.x;
    const int tx = tid & 15;             // 0..15 -> output col group
    const int ty = tid >> 4;             // 0..15 -> output row group

    const float* Ar = A + (long)b * aStride;
    const float* Ai = Ar + NN;
    const float* Xr = X + (long)b * 2 * NN;
    const float* Xi = Xr + NN;

    // Global-load mapping
    const int a_row = tid >> 2;          // 0..63   (row within A tile)
    const int a_k   = (tid & 3) << 2;    // 0,4,8,12 (k offset, float4)
    const int b_row = tid >> 4;          // 0..15   (k row within B tile)
    const int b_col = (tid & 15) << 2;   // 0..60   (col offset, float4)

    const float* Arp = Ar + (long)(bm + a_row) * Nn + a_k;
    const float* Aip = Ai + (long)(bm + a_row) * Nn + a_k;
    const float* Xrp = Xr + (long)b_row * Nn + bn + b_col;
    const float* Xip = Xi + (long)b_row * Nn + bn + b_col;

    float accr[4][4] = {};
    float acci[4][4] = {};

    for (int k0 = 0; k0 < Nn; k0 += BK) {
        // ---- Global -> shared ----
        float4 a4r = *(const float4*)(Arp + k0);
        float4 a4i = *(const float4*)(Aip + k0);
        float4 b4r = *(const float4*)(Xrp + (long)k0 * Nn);
        float4 b4i = *(const float4*)(Xip + (long)k0 * Nn);

        As_r[a_k + 0][a_row] = a4r.x;
        As_r[a_k + 1][a_row] = a4r.y;
        As_r[a_k + 2][a_row] = a4r.z;
        As_r[a_k + 3][a_row] = a4r.w;
        As_i[a_k + 0][a_row] = a4i.x;
        As_i[a_k + 1][a_row] = a4i.y;
        As_i[a_k + 2][a_row] = a4i.z;
        As_i[a_k + 3][a_row] = a4i.w;
        *(float4*)&Bs_r[b_row][b_col] = b4r;
        *(float4*)&Bs_i[b_row][b_col] = b4i;

        __syncthreads();

        // ---- Compute: 64 FFMA per k per thread ----
        #pragma unroll
        for (int k = 0; k < BK; ++k) {
            float4 arv = *(const float4*)&As_r[k][ty << 2];
            float4 aiv = *(const float4*)&As_i[k][ty << 2];
            float4 brv = *(const float4*)&Bs_r[k][tx << 2];
            float4 biv = *(const float4*)&Bs_i[k][tx << 2];
            float ar[4] = {arv.x, arv.y, arv.z, arv.w};
            float ai[4] = {aiv.x, aiv.y, aiv.z, aiv.w};
            float br[4] = {brv.x, brv.y, brv.z, brv.w};
            float bi[4] = {biv.x, biv.y, biv.z, biv.w};

            #pragma unroll
            for (int i = 0; i < 4; ++i) {
                #pragma unroll
                for (int j = 0; j < 4; ++j) {
                    accr[i][j] = fmaf(ar[i],  br[j], accr[i][j]);
                    accr[i][j] = fmaf(-ai[i], bi[j], accr[i][j]);
                    acci[i][j] = fmaf(ar[i],  bi[j], acci[i][j]);
                    acci[i][j] = fmaf(ai[i],  br[j], acci[i][j]);
                }
            }
        }
        __syncthreads();
    }

    // ---- Epilogue: D = C + acc ----
    const int row0 = bm + (ty << 2);
    const int col0 = bn + (tx << 2);
    float* Dr = D + (long)b * 2 * NN;
    float* Di = Dr + NN;

    #pragma unroll
    for (int i = 0; i < 4; ++i) {
        const long off = (long)(row0 + i) * Nn + col0;
        float4 cr = *(const float4*)(C + off);
        float4 ci = *(const float4*)(C + NN + off);
        float4 outr = {accr[i][0] + cr.x, accr[i][1] + cr.y,
                       accr[i][2] + cr.z, accr[i][3] + cr.w};
        float4 outi = {acci[i][0] + ci.x, acci[i][1] + ci.y,
                       acci[i][2] + ci.z, acci[i][3] + ci.w};
        *(float4*)(Dr + off) = outr;
        *(float4*)(Di + off) = outi;
    }
}

// ---------------------------------------------------------------------------
// Host side: Horner's scheme
//   S = C_7
//   for i = 6..0:  S = C_i + S @ X        (complex)
//   out = S
// 7 launches; first one reads C_7 with batch-stride 0 (broadcast never
// materialized). Last one writes straight into d_out.
// ---------------------------------------------------------------------------
extern "C" void kernel_launch(void* const* d_in, const int* in_sizes, int n_in,
                              void* d_out, int out_size)
{
    const float* x      = (const float*)d_in[0];
    const float* coeffs = (const float*)d_in[1];
    // Defensive: identify by element count (x = 64*2*N*N, coeffs = 8*2*N*N)
    if (n_in >= 2 && in_sizes[0] == DEG * 2 * NN) {
        const float* t = x; x = coeffs; coeffs = t;
    }

    float *b0 = nullptr, *b1 = nullptr;
    cudaGetSymbolAddress((void**)&b0, g_buf0);
    cudaGetSymbolAddress((void**)&b1, g_buf1);

    dim3 grid(Nn / BN, Nn / BM, BATCH);   // (8, 8, 64)
    dim3 block(256);

    float* dsts[7] = {b0, b1, b0, b1, b0, b1, (float*)d_out};

    const float* Aptr   = coeffs + (long)7 * 2 * NN;  // S_7 = C_7 (broadcast)
    long         astride = 0;

    for (int t = 0; t < 7; ++t) {
        const float* Cadd = coeffs + (long)(6 - t) * 2 * NN;
        cgemm_horner_kernel<<<grid, block>>>(Aptr, astride, x, Cadd, dsts[t]);
        Aptr    = dsts[t];
        astride = 2L * NN;
    }
}

// round 3
// speedup vs baseline: 2.0190x; 2.0190x over previous
#include <cuda_runtime.h>
#include <cuda_bf16.h>
#include <cstdint>

#define Nn    512
#define NN    (Nn * Nn)
#define BATCH 64
#define KCH   32                 // k per chunk
#define NCHUNK (Nn / KCH)        // 16
#define MAT_B 16384              // one matrix: 128 rows x 128B (hi|lo)
#define STG   65536              // stage: Ar,Ai,Br,Bi
#define SMEM_BYTES (3 * STG + 1024)

// ---------------- global scratch (static __device__: allowed) ----------------
__device__ __nv_bfloat16 g_xt_hi[(size_t)BATCH * 2 * NN];
__device__ __nv_bfloat16 g_xt_lo[(size_t)BATCH * 2 * NN];
__device__ __nv_bfloat16 g_s0_hi[(size_t)BATCH * 2 * NN];
__device__ __nv_bfloat16 g_s0_lo[(size_t)BATCH * 2 * NN];
__device__ __nv_bfloat16 g_s1_hi[(size_t)BATCH * 2 * NN];
__device__ __nv_bfloat16 g_s1_lo[(size_t)BATCH * 2 * NN];
__device__ __nv_bfloat16 g_c7_hi[(size_t)2 * NN];
__device__ __nv_bfloat16 g_c7_lo[(size_t)2 * NN];

// ---------------- helpers ----------------
__device__ __forceinline__ uint32_t smem_u32(const void* p) {
    uint32_t a;
    asm("{ .reg .u64 t; cvta.to.shared.u64 t, %1; cvt.u32.u64 %0, t; }" : "=r"(a) : "l"(p));
    return a;
}
#define CP_ASYNC16(dst, src) \
    asm volatile("cp.async.cg.shared.global [%0], [%1], 16;" :: "r"(dst), "l"(src))
#define CP_COMMIT()  asm volatile("cp.async.commit_group;" ::: "memory")
#define CP_WAIT1()   asm volatile("cp.async.wait_group 1;" ::: "memory")
#define CP_WAIT0()   asm volatile("cp.async.wait_group 0;" ::: "memory")

__device__ __forceinline__ void ldsm4(uint32_t* r, uint32_t addr) {
    asm volatile("ldmatrix.sync.aligned.m8n8.x4.shared.b16 {%0,%1,%2,%3}, [%4];"
                 : "=r"(r[0]), "=r"(r[1]), "=r"(r[2]), "=r"(r[3]) : "r"(addr));
}
__device__ __forceinline__ void mma16816(float* d, const uint32_t* a, const uint32_t* b) {
    asm volatile(
        "mma.sync.aligned.m16n8k16.row.col.f32.bf16.bf16.f32 "
        "{%0,%1,%2,%3}, {%4,%5,%6,%7}, {%8,%9}, {%0,%1,%2,%3};"
        : "+f"(d[0]), "+f"(d[1]), "+f"(d[2]), "+f"(d[3])
        : "r"(a[0]), "r"(a[1]), "r"(a[2]), "r"(a[3]), "r"(b[0]), "r"(b[1]));
}
__device__ __forceinline__ void bsplit(float v, __nv_bfloat16& h, __nv_bfloat16& l) {
    h = __float2bfloat16(v);
    l = __float2bfloat16(v - __bfloat162float(h));
}

// ---------------------------------------------------------------------------
// Precompute: transpose + split X:  xt[b*2+c][n][k] = split(x[b][c][k][n])
// ---------------------------------------------------------------------------
__global__ void split_x_transpose(const float* __restrict__ x,
                                  __nv_bfloat16* __restrict__ xh,
                                  __nv_bfloat16* __restrict__ xl)
{
    __shared__ float t[32][33];
    const int z  = blockIdx.z;
    const int k0 = blockIdx.y * 32;
    const int n0 = blockIdx.x * 32;
    const int tx = threadIdx.x & 31, ty = threadIdx.x >> 5;
    const long zb = (long)z * NN;
    #pragma unroll
    for (int i = 0; i < 4; ++i)
        t[ty + 8 * i][tx] = x[zb + (long)(k0 + ty + 8 * i) * Nn + n0 + tx];
    __syncthreads();
    #pragma unroll
    for (int i = 0; i < 4; ++i) {
        const int n = n0 + ty + 8 * i, k = k0 + tx;
        __nv_bfloat16 h, l;
        bsplit(t[tx][ty + 8 * i], h, l);
        xh[zb + (long)n * Nn + k] = h;
        xl[zb + (long)n * Nn + k] = l;
    }
}

__global__ void split_c7(const float* __restrict__ c7,
                         __nv_bfloat16* __restrict__ h, __nv_bfloat16* __restrict__ l)
{
    const int i = blockIdx.x * 256 + threadIdx.x;
    if (i < 2 * NN) {
        __nv_bfloat16 hh, ll;
        bsplit(c7[i], hh, ll);
        h[i] = hh; l[i] = ll;
    }
}

// ---------------------------------------------------------------------------
// Fused complex GEMM, bf16x3 split, mma.sync.m16n8k16.
// Each CTA computes ONE output component (comp = blockIdx.x & 1):
//   comp0: D = Cr + Ar.Xr - Ai.Xi     comp1: D = Ci + Ar.Xi + Ai.Xr
// A/B smem rows: 128 bytes = [hi 32bf16 | lo 32bf16], SW128 swizzled.
// ---------------------------------------------------------------------------
__global__ void __launch_bounds__(256, 1) cgemm_mma(
    const __nv_bfloat16* __restrict__ aHi, const __nv_bfloat16* __restrict__ aLo, long aStride,
    const __nv_bfloat16* __restrict__ xHi, const __nv_bfloat16* __restrict__ xLo,
    const float* __restrict__ C,
    float* __restrict__ outF,
    __nv_bfloat16* __restrict__ outHi, __nv_bfloat16* __restrict__ outLo,
    int isFinal)
{
    extern __shared__ char smraw[];
    const uint32_t sbase = (smem_u32(smraw) + 1023) & ~1023u;

    const int tid  = threadIdx.x;
    const int lane = tid & 31, wid = tid >> 5;
    const int warp_m = wid & 3, warp_n = wid >> 2;
    const int b    = blockIdx.z;
    const int comp = blockIdx.x & 1;
    const int bn   = (blockIdx.x >> 1) * 128;
    const int bm   = blockIdx.y * 128;

    // ---- cp.async per-thread constants ----
    // id = tid + it*256: q=tid&3 (16B chunk), half=(tid>>2)&1, rowt=tid>>3 (0..31)
    const int q = tid & 3, half = (tid >> 2) & 1, rowt = tid >> 3;
    const __nv_bfloat16* pA = (half ? aLo : aHi) + (long)b * aStride + (long)(bm + rowt) * Nn + q * 8;
    const __nv_bfloat16* pB = (half ? xLo : xHi) + (long)(2 * b) * NN + (long)(bn + rowt) * Nn + q * 8;
    uint32_t d0 = (uint32_t)(rowt * 128 + half * 64 + q * 16);
    const uint32_t dbase = d0 ^ (uint32_t)((rowt & 7) << 4);

    // ---- ldmatrix per-lane constants ----
    const uint32_t amask = (uint32_t)((lane & 7) << 4);
    const uint32_t abase = (uint32_t)((warp_m * 32 + (lane & 15)) * 128 + (lane >> 4) * 16);
    const uint32_t bbase = (uint32_t)((warp_n * 64 + ((lane & 7) | ((lane >> 1) & 8))) * 128
                                      + ((lane >> 3) & 1) * 16);
    const uint32_t b1off = 32768u + (comp ? 16384u : 0u);
    const uint32_t b2off = 32768u + (comp ? 0u : 16384u);

    float acc[2][8][4];
    #pragma unroll
    for (int i = 0; i < 2; ++i)
        #pragma unroll
        for (int j = 0; j < 8; ++j)
            #pragma unroll
            for (int k = 0; k < 4; ++k) acc[i][j][k] = 0.f;

    // ---- issue one chunk's cp.asyncs ----
    auto issue = [&](int c) {
        const __nv_bfloat16* sA = pA + c * KCH;
        const __nv_bfloat16* sB = pB + c * KCH;
        const uint32_t sd = sbase + (uint32_t)(c % 3) * STG + dbase;
        #pragma unroll
        for (int it = 0; it < 16; ++it) {
            const __nv_bfloat16* src =
                (it < 8 ? sA : sB) + ((it & 4) ? NN : 0) + (it & 3) * (32 * Nn);
            const uint32_t dst = sd + (uint32_t)(it >> 2) * MAT_B + (uint32_t)(it & 3) * 4096u;
            CP_ASYNC16(dst, src);
        }
        CP_COMMIT();
    };

    issue(0);
    issue(1);

    for (int c = 0; c < NCHUNK; ++c) {
        if (c < NCHUNK - 1) CP_WAIT1(); else CP_WAIT0();
        __syncthreads();

        const uint32_t st = sbase + (uint32_t)(c % 3) * STG;
        #pragma unroll
        for (int sl = 0; sl < 2; ++sl) {
            uint32_t a_rh[2][4], a_rl[2][4], a_ih[2][4], a_il[2][4];
            #pragma unroll
            for (int mt = 0; mt < 2; ++mt) {
                const uint32_t rh = (abase + (uint32_t)mt * 2048u + (uint32_t)sl * 32u) ^ amask;
                ldsm4(a_rh[mt], st + rh);
                ldsm4(a_rl[mt], st + (rh ^ 64u));
                ldsm4(a_ih[mt], st + MAT_B + rh);
                ldsm4(a_il[mt], st + MAT_B + (rh ^ 64u));
            }
            if (comp == 0) {        // fold the minus sign of Ai.Xi
                #pragma unroll
                for (int mt = 0; mt < 2; ++mt)
                    #pragma unroll
                    for (int j = 0; j < 4; ++j) {
                        a_ih[mt][j] ^= 0x80008000u;
                        a_il[mt][j] ^= 0x80008000u;
                    }
            }
            #pragma unroll
            for (int ng = 0; ng < 4; ++ng) {
                const uint32_t bh = (bbase + (uint32_t)ng * 2048u + (uint32_t)sl * 32u) ^ amask;
                uint32_t b1h[4], b1l[4], b2h[4], b2l[4];
                ldsm4(b1h, st + b1off + bh);
                ldsm4(b1l, st + b1off + (bh ^ 64u));
                ldsm4(b2h, st + b2off + bh);
                ldsm4(b2l, st + b2off + (bh ^ 64u));
                #pragma unroll
                for (int mt = 0; mt < 2; ++mt)
                    #pragma unroll
                    for (int nt = 0; nt < 2; ++nt) {
                        float* ac = acc[mt][ng * 2 + nt];
                        mma16816(ac, a_rh[mt], b1h + nt * 2);
                        mma16816(ac, a_rh[mt], b1l + nt * 2);
                        mma16816(ac, a_rl[mt], b1h + nt * 2);
                        mma16816(ac, a_ih[mt], b2h + nt * 2);
                        mma16816(ac, a_ih[mt], b2l + nt * 2);
                        mma16816(ac, a_il[mt], b2h + nt * 2);
                    }
            }
        }
        __syncthreads();
        if (c + 2 < NCHUNK) issue(c + 2);
    }

    // ---- epilogue: D = C + acc; emit split(D) or fp32 ----
    const int tq = lane >> 2, tr = (lane & 3) * 2;
    #pragma unroll
    for (int mt = 0; mt < 2; ++mt)
        #pragma unroll
        for (int nt = 0; nt < 8; ++nt) {
            const int r0 = bm + warp_m * 32 + mt * 16 + tq;
            const int c0 = bn + warp_n * 64 + nt * 8 + tr;
            const float* a4 = acc[mt][nt];
            #pragma unroll
            for (int h = 0; h < 2; ++h) {
                const int r = r0 + h * 8;
                const long co = (long)comp * NN + (long)r * Nn + c0;
                const float2 cc = *(const float2*)(C + co);
                const float v0 = a4[h * 2] + cc.x;
                const float v1 = a4[h * 2 + 1] + cc.y;
                const long oo = ((long)b * 2 + comp) * NN + (long)r * Nn + c0;
                if (isFinal) {
                    *(float2*)(outF + oo) = make_float2(v0, v1);
                } else {
                    __nv_bfloat16 h0, l0, h1, l1;
                    bsplit(v0, h0, l0);
                    bsplit(v1, h1, l1);
                    __nv_bfloat162 hv; hv.x = h0; hv.y = h1;
                    __nv_bfloat162 lv; lv.x = l0; lv.y = l1;
                    *(__nv_bfloat162*)(outHi + oo) = hv;
                    *(__nv_bfloat162*)(outLo + oo) = lv;
                }
            }
        }
}

// ---------------------------------------------------------------------------
extern "C" void kernel_launch(void* const* d_in, const int* in_sizes, int n_in,
                              void* d_out, int out_size)
{
    const float* x      = (const float*)d_in[0];
    const float* coeffs = (const float*)d_in[1];
    if (n_in >= 2 && in_sizes[0] == 8 * 2 * NN) {   // defensive swap
        const float* t = x; x = coeffs; coeffs = t;
    }

    __nv_bfloat16 *xtH, *xtL, *s0H, *s0L, *s1H, *s1L, *c7H, *c7L;
    cudaGetSymbolAddress((void**)&xtH, g_xt_hi);
    cudaGetSymbolAddress((void**)&xtL, g_xt_lo);
    cudaGetSymbolAddress((void**)&s0H, g_s0_hi);
    cudaGetSymbolAddress((void**)&s0L, g_s0_lo);
    cudaGetSymbolAddress((void**)&s1H, g_s1_hi);
    cudaGetSymbolAddress((void**)&s1L, g_s1_lo);
    cudaGetSymbolAddress((void**)&c7H, g_c7_hi);
    cudaGetSymbolAddress((void**)&c7L, g_c7_lo);

    cudaFuncSetAttribute(cgemm_mma, cudaFuncAttributeMaxDynamicSharedMemorySize, SMEM_BYTES);

    split_x_transpose<<<dim3(16, 16, 128), 256>>>(x, xtH, xtL);
    split_c7<<<(2 * NN + 255) / 256, 256>>>(coeffs + (long)7 * 2 * NN, c7H, c7L);

    dim3 grid(8, 4, BATCH);   // x = ncol*2 + comp
    dim3 block(256);

    const __nv_bfloat16* aH = c7H;
    const __nv_bfloat16* aL = c7L;
    long aStride = 0;
    __nv_bfloat16* dstH[7] = {s0H, s1H, s0H, s1H, s0H, s1H, nullptr};
    __nv_bfloat16* dstL[7] = {s0L, s1L, s0L, s1L, s0L, s1L, nullptr};

    for (int t = 0; t < 7; ++t) {
        const float* Ct = coeffs + (long)(6 - t) * 2 * NN;
        const int fin = (t == 6);
        cgemm_mma<<<grid, block, SMEM_BYTES>>>(
            aH, aL, aStride, xtH, xtL, Ct,
            fin ? (float*)d_out : nullptr, dstH[t], dstL[t], fin);
        aH = dstH[t]; aL = dstL[t];
        aStride = 2L * NN;
    }
}

// round 4
// speedup vs baseline: 2.4852x; 1.2309x over previous
#include <cuda_runtime.h>
#include <cuda_bf16.h>
#include <cstdint>

#define Nn    512
#define NN    (Nn * Nn)
#define BATCH 64
#define KCH   32
#define NCHUNK (Nn / KCH)        // 16
#define BM 128
#define BN 64
#define A_MAT 16384              // 128 rows x 128B (hi|lo)
#define B_MAT 8192               // 64 rows x 128B
#define STG_B (2*A_MAT + 2*B_MAT)   // 49152
#define NSTG 4
#define SMEM_BYTES (NSTG * STG_B + 1024)

// ---------------- global scratch ----------------
__device__ __nv_bfloat16 g_xt_hi[(size_t)BATCH * 2 * NN];
__device__ __nv_bfloat16 g_xt_lo[(size_t)BATCH * 2 * NN];
__device__ __nv_bfloat16 g_s0_hi[(size_t)BATCH * 2 * NN];
__device__ __nv_bfloat16 g_s0_lo[(size_t)BATCH * 2 * NN];
__device__ __nv_bfloat16 g_s1_hi[(size_t)BATCH * 2 * NN];
__device__ __nv_bfloat16 g_s1_lo[(size_t)BATCH * 2 * NN];
__device__ __nv_bfloat16 g_c7_hi[(size_t)2 * NN];
__device__ __nv_bfloat16 g_c7_lo[(size_t)2 * NN];

// ---------------- helpers ----------------
__device__ __forceinline__ uint32_t smem_u32(const void* p) {
    uint32_t a;
    asm("{ .reg .u64 t; cvta.to.shared.u64 t, %1; cvt.u32.u64 %0, t; }" : "=r"(a) : "l"(p));
    return a;
}
#define CP_ASYNC16(dst, src) \
    asm volatile("cp.async.cg.shared.global [%0], [%1], 16;" :: "r"(dst), "l"(src))
#define CP_COMMIT()  asm volatile("cp.async.commit_group;" ::: "memory")
#define CP_WAIT2()   asm volatile("cp.async.wait_group 2;" ::: "memory")
#define CP_WAIT1()   asm volatile("cp.async.wait_group 1;" ::: "memory")
#define CP_WAIT0()   asm volatile("cp.async.wait_group 0;" ::: "memory")

__device__ __forceinline__ void ldsm4(uint32_t* r, uint32_t addr) {
    asm volatile("ldmatrix.sync.aligned.m8n8.x4.shared.b16 {%0,%1,%2,%3}, [%4];"
                 : "=r"(r[0]), "=r"(r[1]), "=r"(r[2]), "=r"(r[3]) : "r"(addr));
}
__device__ __forceinline__ void mma16816(float* d, const uint32_t* a, const uint32_t* b) {
    asm volatile(
        "mma.sync.aligned.m16n8k16.row.col.f32.bf16.bf16.f32 "
        "{%0,%1,%2,%3}, {%4,%5,%6,%7}, {%8,%9}, {%0,%1,%2,%3};"
        : "+f"(d[0]), "+f"(d[1]), "+f"(d[2]), "+f"(d[3])
        : "r"(a[0]), "r"(a[1]), "r"(a[2]), "r"(a[3]), "r"(b[0]), "r"(b[1]));
}
__device__ __forceinline__ void bsplit(float v, __nv_bfloat16& h, __nv_bfloat16& l) {
    h = __float2bfloat16(v);
    l = __float2bfloat16(v - __bfloat162float(h));
}

// ---------------------------------------------------------------------------
__global__ void split_x_transpose(const float* __restrict__ x,
                                  __nv_bfloat16* __restrict__ xh,
                                  __nv_bfloat16* __restrict__ xl)
{
    __shared__ float t[32][33];
    const int z  = blockIdx.z;
    const int k0 = blockIdx.y * 32;
    const int n0 = blockIdx.x * 32;
    const int tx = threadIdx.x & 31, ty = threadIdx.x >> 5;
    const long zb = (long)z * NN;
    #pragma unroll
    for (int i = 0; i < 4; ++i)
        t[ty + 8 * i][tx] = x[zb + (long)(k0 + ty + 8 * i) * Nn + n0 + tx];
    __syncthreads();
    #pragma unroll
    for (int i = 0; i < 4; ++i) {
        const int n = n0 + ty + 8 * i, k = k0 + tx;
        __nv_bfloat16 h, l;
        bsplit(t[tx][ty + 8 * i], h, l);
        xh[zb + (long)n * Nn + k] = h;
        xl[zb + (long)n * Nn + k] = l;
    }
}

__global__ void split_c7(const float* __restrict__ c7,
                         __nv_bfloat16* __restrict__ h, __nv_bfloat16* __restrict__ l)
{
    const int i = blockIdx.x * 256 + threadIdx.x;
    if (i < 2 * NN) {
        __nv_bfloat16 hh, ll;
        bsplit(c7[i], hh, ll);
        h[i] = hh; l[i] = ll;
    }
}

// ---------------------------------------------------------------------------
// Fused complex GEMM, bf16x3 split, both components per CTA, 3 accumulators:
//   accRR = Ar.Xr ; accII = Ai.Xi ; accMix = Ar.Xi + Ai.Xr
//   Dr = accRR - accII + Cr ; Di = accMix + Ci
// 512 threads, tile 128x64, warp tile 32x16, 4-stage cp.async pipeline.
// ---------------------------------------------------------------------------
__global__ void __launch_bounds__(512, 1) cgemm_mma(
    const __nv_bfloat16* __restrict__ aHi, const __nv_bfloat16* __restrict__ aLo, long aStride,
    const __nv_bfloat16* __restrict__ xHi, const __nv_bfloat16* __restrict__ xLo,
    const float* __restrict__ C,
    float* __restrict__ outF,
    __nv_bfloat16* __restrict__ outHi, __nv_bfloat16* __restrict__ outLo,
    int isFinal)
{
    extern __shared__ char smraw[];
    const uint32_t sbase = (smem_u32(smraw) + 1023) & ~1023u;

    const int tid  = threadIdx.x;
    const int lane = tid & 31, wid = tid >> 5;
    const int warp_m = wid & 3;          // 4 m-tiles of 32 rows
    const int warp_n = wid >> 2;         // 4 n-tiles of 16 cols
    const int b  = blockIdx.z;
    const int bn = blockIdx.x * BN;
    const int bm = blockIdx.y * BM;

    // ---- cp.async per-thread constants ----
    const int q = tid & 3, half = (tid >> 2) & 1, rowt = tid >> 3;   // rowt in [0,64)
    const __nv_bfloat16* pA = (half ? aLo : aHi) + (long)b * aStride + (long)(bm + rowt) * Nn + q * 8;
    const __nv_bfloat16* pB = (half ? xLo : xHi) + (long)(2 * b) * NN + (long)(bn + rowt) * Nn + q * 8;
    const uint32_t d0    = (uint32_t)(rowt * 128 + half * 64 + q * 16);
    const uint32_t dbase = d0 ^ (uint32_t)((rowt & 7) << 4);

    // ---- ldmatrix per-lane constants ----
    const uint32_t amask = (uint32_t)((lane & 7) << 4);
    const uint32_t abase = (uint32_t)((warp_m * 32 + (lane & 15)) * 128 + (lane >> 4) * 16);
    const uint32_t bbase = (uint32_t)((warp_n * 16 + ((lane & 7) | ((lane >> 1) & 8))) * 128
                                      + ((lane >> 3) & 1) * 16);

    float accRR[2][2][4], accII[2][2][4], accMix[2][2][4];
    #pragma unroll
    for (int i = 0; i < 2; ++i)
        #pragma unroll
        for (int j = 0; j < 2; ++j)
            #pragma unroll
            for (int k = 0; k < 4; ++k) {
                accRR[i][j][k] = 0.f; accII[i][j][k] = 0.f; accMix[i][j][k] = 0.f;
            }

    // ---- issue one chunk (6 x 16B per thread = 48KB stage) ----
    auto issue = [&](int c) {
        const int k0 = c * KCH;
        const uint32_t sd = sbase + (uint32_t)(c & 3) * STG_B + dbase;
        const __nv_bfloat16* sA = pA + k0;
        const __nv_bfloat16* sB = pB + k0;
        CP_ASYNC16(sd,                 sA);                       // Ar rows [0,64)
        CP_ASYNC16(sd + 8192,          sA + 64L * Nn);            // Ar rows [64,128)
        CP_ASYNC16(sd + 16384,         sA + NN);                  // Ai rows [0,64)
        CP_ASYNC16(sd + 16384 + 8192,  sA + NN + 64L * Nn);       // Ai rows [64,128)
        CP_ASYNC16(sd + 32768,         sB);                       // Xr
        CP_ASYNC16(sd + 40960,         sB + NN);                  // Xi
        CP_COMMIT();
    };

    issue(0); issue(1); issue(2);

    for (int c = 0; c < NCHUNK; ++c) {
        if (c < NCHUNK - 2)      CP_WAIT2();
        else if (c == NCHUNK - 2) CP_WAIT1();
        else                      CP_WAIT0();
        __syncthreads();

        const uint32_t st = sbase + (uint32_t)(c & 3) * STG_B;
        #pragma unroll
        for (int sl = 0; sl < 2; ++sl) {
            uint32_t arh[2][4], arl[2][4], aih[2][4], ail[2][4];
            #pragma unroll
            for (int mt = 0; mt < 2; ++mt) {
                const uint32_t rh = (abase + (uint32_t)mt * 2048u + (uint32_t)sl * 32u) ^ amask;
                ldsm4(arh[mt], st + rh);
                ldsm4(arl[mt], st + (rh ^ 64u));
                ldsm4(aih[mt], st + 16384u + rh);
                ldsm4(ail[mt], st + 16384u + (rh ^ 64u));
            }
            const uint32_t bb = (bbase + (uint32_t)sl * 32u) ^ amask;

            {   // ---- B = Xr : feed accRR (Ar.Xr) and accMix (Ai.Xr) ----
                uint32_t bh[4], bl[4];
                ldsm4(bh, st + 32768u + bb);
                ldsm4(bl, st + 32768u + (bb ^ 64u));
                #pragma unroll
                for (int mt = 0; mt < 2; ++mt)
                    #pragma unroll
                    for (int nt = 0; nt < 2; ++nt) {
                        mma16816(accRR[mt][nt],  arh[mt], bh + nt * 2);
                        mma16816(accRR[mt][nt],  arh[mt], bl + nt * 2);
                        mma16816(accRR[mt][nt],  arl[mt], bh + nt * 2);
                        mma16816(accMix[mt][nt], aih[mt], bh + nt * 2);
                        mma16816(accMix[mt][nt], aih[mt], bl + nt * 2);
                        mma16816(accMix[mt][nt], ail[mt], bh + nt * 2);
                    }
            }
            {   // ---- B = Xi : feed accII (Ai.Xi) and accMix (Ar.Xi) ----
                uint32_t bh[4], bl[4];
                ldsm4(bh, st + 40960u + bb);
                ldsm4(bl, st + 40960u + (bb ^ 64u));
                #pragma unroll
                for (int mt = 0; mt < 2; ++mt)
                    #pragma unroll
                    for (int nt = 0; nt < 2; ++nt) {
                        mma16816(accII[mt][nt],  aih[mt], bh + nt * 2);
                        mma16816(accII[mt][nt],  aih[mt], bl + nt * 2);
                        mma16816(accII[mt][nt],  ail[mt], bh + nt * 2);
                        mma16816(accMix[mt][nt], arh[mt], bh + nt * 2);
                        mma16816(accMix[mt][nt], arh[mt], bl + nt * 2);
                        mma16816(accMix[mt][nt], arl[mt], bh + nt * 2);
                    }
            }
        }
        if (c + 3 < NCHUNK) issue(c + 3);
    }

    // ---- epilogue: Dr = RR - II + Cr ; Di = Mix + Ci ----
    const int tq = lane >> 2, tr = (lane & 3) * 2;
    #pragma unroll
    for (int mt = 0; mt < 2; ++mt)
        #pragma unroll
        for (int nt = 0; nt < 2; ++nt)
            #pragma unroll
            for (int h = 0; h < 2; ++h) {
                const int r  = bm + warp_m * 32 + mt * 16 + h * 8 + tq;
                const int c0 = bn + warp_n * 16 + nt * 8 + tr;
                const long co = (long)r * Nn + c0;
                const float2 cr = *(const float2*)(C + co);
                const float2 ci = *(const float2*)(C + NN + co);
                const float vr0 = accRR[mt][nt][2*h]   - accII[mt][nt][2*h]   + cr.x;
                const float vr1 = accRR[mt][nt][2*h+1] - accII[mt][nt][2*h+1] + cr.y;
                const float vi0 = accMix[mt][nt][2*h]   + ci.x;
                const float vi1 = accMix[mt][nt][2*h+1] + ci.y;
                const long or_ = ((long)b * 2 + 0) * NN + co;
                const long oi_ = ((long)b * 2 + 1) * NN + co;
                if (isFinal) {
                    *(float2*)(outF + or_) = make_float2(vr0, vr1);
                    *(float2*)(outF + oi_) = make_float2(vi0, vi1);
                } else {
                    __nv_bfloat16 h0, l0, h1, l1;
                    bsplit(vr0, h0, l0); bsplit(vr1, h1, l1);
                    __nv_bfloat162 hv; hv.x = h0; hv.y = h1;
                    __nv_bfloat162 lv; lv.x = l0; lv.y = l1;
                    *(__nv_bfloat162*)(outHi + or_) = hv;
                    *(__nv_bfloat162*)(outLo + or_) = lv;
                    bsplit(vi0, h0, l0); bsplit(vi1, h1, l1);
                    hv.x = h0; hv.y = h1; lv.x = l0; lv.y = l1;
                    *(__nv_bfloat162*)(outHi + oi_) = hv;
                    *(__nv_bfloat162*)(outLo + oi_) = lv;
                }
            }
}

// ---------------------------------------------------------------------------
extern "C" void kernel_launch(void* const* d_in, const int* in_sizes, int n_in,
                              void* d_out, int out_size)
{
    const float* x      = (const float*)d_in[0];
    const float* coeffs = (const float*)d_in[1];
    if (n_in >= 2 && in_sizes[0] == 8 * 2 * NN) {
        const float* t = x; x = coeffs; coeffs = t;
    }

    __nv_bfloat16 *xtH, *xtL, *s0H, *s0L, *s1H, *s1L, *c7H, *c7L;
    cudaGetSymbolAddress((void**)&xtH, g_xt_hi);
    cudaGetSymbolAddress((void**)&xtL, g_xt_lo);
    cudaGetSymbolAddress((void**)&s0H, g_s0_hi);
    cudaGetSymbolAddress((void**)&s0L, g_s0_lo);
    cudaGetSymbolAddress((void**)&s1H, g_s1_hi);
    cudaGetSymbolAddress((void**)&s1L, g_s1_lo);
    cudaGetSymbolAddress((void**)&c7H, g_c7_hi);
    cudaGetSymbolAddress((void**)&c7L, g_c7_lo);

    cudaFuncSetAttribute(cgemm_mma, cudaFuncAttributeMaxDynamicSharedMemorySize, SMEM_BYTES);

    split_x_transpose<<<dim3(16, 16, 128), 256>>>(x, xtH, xtL);
    split_c7<<<(2 * NN + 255) / 256, 256>>>(coeffs + (long)7 * 2 * NN, c7H, c7L);

    dim3 grid(Nn / BN, Nn / BM, BATCH);   // (8, 4, 64)
    dim3 block(512);

    const __nv_bfloat16* aH = c7H;
    const __nv_bfloat16* aL = c7L;
    long aStride = 0;
    __nv_bfloat16* dstH[7] = {s0H, s1H, s0H, s1H, s0H, s1H, nullptr};
    __nv_bfloat16* dstL[7] = {s0L, s1L, s0L, s1L, s0L, s1L, nullptr};

    for (int t = 0; t < 7; ++t) {
        const float* Ct = coeffs + (long)(6 - t) * 2 * NN;
        const int fin = (t == 6);
        cgemm_mma<<<grid, block, SMEM_BYTES>>>(
            aH, aL, aStride, xtH, xtL, Ct,
            fin ? (float*)d_out : nullptr, dstH[t], dstL[t], fin);
        aH = dstH[t]; aL = dstL[t];
        aStride = 2L * NN;
    }
}

// round 5
// speedup vs baseline: 2.6119x; 1.0510x over previous
#include <cuda_runtime.h>
#include <cuda_bf16.h>
#include <cstdint>

#define Nn    512
#define NN    (Nn * Nn)
#define BATCH 64
#define KCH   32
#define NCHUNK (Nn / KCH)        // 16
#define BM 64
#define BN 64
#define MAT_B 8192               // 64 rows x 128B (hi|lo)
#define STG_B (4 * MAT_B)        // 32768: Ar, Ai, Xr, Xi
#define NSTG 3
#define SMEM_BYTES (NSTG * STG_B + 1024)

// ---------------- global scratch ----------------
__device__ __nv_bfloat16 g_xt_hi[(size_t)BATCH * 2 * NN];
__device__ __nv_bfloat16 g_xt_lo[(size_t)BATCH * 2 * NN];
__device__ __nv_bfloat16 g_s0_hi[(size_t)BATCH * 2 * NN];
__device__ __nv_bfloat16 g_s0_lo[(size_t)BATCH * 2 * NN];
__device__ __nv_bfloat16 g_s1_hi[(size_t)BATCH * 2 * NN];
__device__ __nv_bfloat16 g_s1_lo[(size_t)BATCH * 2 * NN];
__device__ __nv_bfloat16 g_c7_hi[(size_t)2 * NN];
__device__ __nv_bfloat16 g_c7_lo[(size_t)2 * NN];

// ---------------- helpers ----------------
__device__ __forceinline__ uint32_t smem_u32(const void* p) {
    uint32_t a;
    asm("{ .reg .u64 t; cvta.to.shared.u64 t, %1; cvt.u32.u64 %0, t; }" : "=r"(a) : "l"(p));
    return a;
}
#define CP_ASYNC16(dst, src) \
    asm volatile("cp.async.cg.shared.global [%0], [%1], 16;" :: "r"(dst), "l"(src))
#define CP_COMMIT()  asm volatile("cp.async.commit_group;" ::: "memory")
#define CP_WAIT1()   asm volatile("cp.async.wait_group 1;" ::: "memory")
#define CP_WAIT0()   asm volatile("cp.async.wait_group 0;" ::: "memory")

__device__ __forceinline__ void ldsm4(uint32_t* r, uint32_t addr) {
    asm volatile("ldmatrix.sync.aligned.m8n8.x4.shared.b16 {%0,%1,%2,%3}, [%4];"
                 : "=r"(r[0]), "=r"(r[1]), "=r"(r[2]), "=r"(r[3]) : "r"(addr));
}
__device__ __forceinline__ void mma16816(float* d, const uint32_t* a, const uint32_t* b) {
    asm volatile(
        "mma.sync.aligned.m16n8k16.row.col.f32.bf16.bf16.f32 "
        "{%0,%1,%2,%3}, {%4,%5,%6,%7}, {%8,%9}, {%0,%1,%2,%3};"
        : "+f"(d[0]), "+f"(d[1]), "+f"(d[2]), "+f"(d[3])
        : "r"(a[0]), "r"(a[1]), "r"(a[2]), "r"(a[3]), "r"(b[0]), "r"(b[1]));
}
__device__ __forceinline__ void bsplit(float v, __nv_bfloat16& h, __nv_bfloat16& l) {
    h = __float2bfloat16(v);
    l = __float2bfloat16(v - __bfloat162float(h));
}

// ---------------------------------------------------------------------------
__global__ void split_x_transpose(const float* __restrict__ x,
                                  __nv_bfloat16* __restrict__ xh,
                                  __nv_bfloat16* __restrict__ xl)
{
    __shared__ float t[32][33];
    const int z  = blockIdx.z;
    const int k0 = blockIdx.y * 32;
    const int n0 = blockIdx.x * 32;
    const int tx = threadIdx.x & 31, ty = threadIdx.x >> 5;
    const long zb = (long)z * NN;
    #pragma unroll
    for (int i = 0; i < 4; ++i)
        t[ty + 8 * i][tx] = x[zb + (long)(k0 + ty + 8 * i) * Nn + n0 + tx];
    __syncthreads();
    #pragma unroll
    for (int i = 0; i < 4; ++i) {
        const int n = n0 + ty + 8 * i, k = k0 + tx;
        __nv_bfloat16 h, l;
        bsplit(t[tx][ty + 8 * i], h, l);
        xh[zb + (long)n * Nn + k] = h;
        xl[zb + (long)n * Nn + k] = l;
    }
}

__global__ void split_c7(const float* __restrict__ c7,
                         __nv_bfloat16* __restrict__ h, __nv_bfloat16* __restrict__ l)
{
    const int i = blockIdx.x * 256 + threadIdx.x;
    if (i < 2 * NN) {
        __nv_bfloat16 hh, ll;
        bsplit(c7[i], hh, ll);
        h[i] = hh; l[i] = ll;
    }
}

// ---------------------------------------------------------------------------
// Fused complex GEMM, bf16x3 split, 3 accumulators, 64x64 tile, 256 threads,
// 2 CTAs/SM, 3-stage cp.async pipeline.
//   accRR = Ar.Xr ; accII = Ai.Xi ; accMix = Ar.Xi + Ai.Xr
//   Dr = accRR - accII + Cr ; Di = accMix + Ci
// ---------------------------------------------------------------------------
__global__ void __launch_bounds__(256, 2) cgemm_mma(
    const __nv_bfloat16* __restrict__ aHi, const __nv_bfloat16* __restrict__ aLo, long aStride,
    const __nv_bfloat16* __restrict__ xHi, const __nv_bfloat16* __restrict__ xLo,
    const float* __restrict__ C,
    float* __restrict__ outF,
    __nv_bfloat16* __restrict__ outHi, __nv_bfloat16* __restrict__ outLo,
    int isFinal)
{
    extern __shared__ char smraw[];
    const uint32_t sbase = (smem_u32(smraw) + 1023) & ~1023u;

    const int tid  = threadIdx.x;
    const int lane = tid & 31, wid = tid >> 5;
    const int warp_m = wid & 3;          // 4 m-tiles of 16 rows
    const int warp_n = wid >> 2;         // 2 n-tiles of 32 cols
    const int b  = blockIdx.z;
    const int bn = blockIdx.x * BN;
    const int bm = blockIdx.y * BM;

    // ---- cp.async per-thread constants: 8 x 16B per thread per chunk ----
    const int q = tid & 7, rowt = tid >> 3;         // q: 16B chunk in row, rowt: 0..31
    const __nv_bfloat16* srcs[8];
    uint32_t dsts[8];
    #pragma unroll
    for (int it = 0; it < 8; ++it) {
        const int mat = it >> 1, rhalf = it & 1;
        const int row = rowt + rhalf * 32;
        const bool isA = (mat < 2);
        const int comp = mat & 1;
        const __nv_bfloat16* hi = isA ? aHi : xHi;
        const __nv_bfloat16* lo = isA ? aLo : xLo;
        const long off = isA
            ? (long)b * aStride + (long)comp * NN + (long)(bm + row) * Nn
            : ((long)(2 * b) + comp) * NN + (long)(bn + row) * Nn;
        srcs[it] = (q < 4 ? hi : lo) + off + (q & 3) * 8;
        dsts[it] = (uint32_t)(mat * MAT_B) +
                   (((uint32_t)(row * 128 + q * 16)) ^ (uint32_t)((row & 7) << 4));
    }

    auto issue = [&](int c) {
        const uint32_t sd = sbase + (uint32_t)(c % NSTG) * STG_B;
        const long kadd = (long)c * KCH;
        #pragma unroll
        for (int it = 0; it < 8; ++it)
            CP_ASYNC16(sd + dsts[it], srcs[it] + kadd);
        CP_COMMIT();
    };

    // ---- ldmatrix per-lane constants ----
    const uint32_t amask = (uint32_t)((lane & 7) << 4);
    const uint32_t abase = (uint32_t)((warp_m * 16 + (lane & 15)) * 128 + (lane >> 4) * 16);
    const uint32_t brow  = (uint32_t)((lane & 7) | ((lane >> 1) & 8));
    const uint32_t bcol  = (uint32_t)(((lane >> 3) & 1) * 16);

    float accRR[4][4], accII[4][4], accMix[4][4];
    #pragma unroll
    for (int j = 0; j < 4; ++j)
        #pragma unroll
        for (int k = 0; k < 4; ++k) {
            accRR[j][k] = 0.f; accII[j][k] = 0.f; accMix[j][k] = 0.f;
        }

    issue(0); issue(1);

    for (int c = 0; c < NCHUNK; ++c) {
        if (c < NCHUNK - 1) CP_WAIT1(); else CP_WAIT0();
        __syncthreads();
        if (c + 2 < NCHUNK) issue(c + 2);   // stage (c+2)%3 fully consumed at c-1

        const uint32_t st = sbase + (uint32_t)(c % NSTG) * STG_B;
        #pragma unroll
        for (int sl = 0; sl < 2; ++sl) {
            uint32_t arh[4], arl[4], aih[4], ail[4];
            const uint32_t rh = (abase + (uint32_t)sl * 32u) ^ amask;
            ldsm4(arh, st + rh);
            ldsm4(arl, st + (rh ^ 64u));
            ldsm4(aih, st + MAT_B + rh);
            ldsm4(ail, st + MAT_B + (rh ^ 64u));

            #pragma unroll
            for (int ng = 0; ng < 2; ++ng) {
                const uint32_t bb =
                    ((uint32_t)((warp_n * 32 + ng * 16 + brow) * 128) + bcol
                     + (uint32_t)sl * 32u) ^ amask;
                {   // B = Xr: accRR (Ar.Xr), accMix (Ai.Xr)
                    uint32_t bh[4], bl[4];
                    ldsm4(bh, st + 2u * MAT_B + bb);
                    ldsm4(bl, st + 2u * MAT_B + (bb ^ 64u));
                    #pragma unroll
                    for (int nt = 0; nt < 2; ++nt) {
                        float* rr = accRR[ng * 2 + nt];
                        float* mx = accMix[ng * 2 + nt];
                        mma16816(rr, arh, bh + nt * 2);
                        mma16816(rr, arh, bl + nt * 2);
                        mma16816(rr, arl, bh + nt * 2);
                        mma16816(mx, aih, bh + nt * 2);
                        mma16816(mx, aih, bl + nt * 2);
                        mma16816(mx, ail, bh + nt * 2);
                    }
                }
                {   // B = Xi: accII (Ai.Xi), accMix (Ar.Xi)
                    uint32_t bh[4], bl[4];
                    ldsm4(bh, st + 3u * MAT_B + bb);
                    ldsm4(bl, st + 3u * MAT_B + (bb ^ 64u));
                    #pragma unroll
                    for (int nt = 0; nt < 2; ++nt) {
                        float* ii = accII[ng * 2 + nt];
                        float* mx = accMix[ng * 2 + nt];
                        mma16816(ii, aih, bh + nt * 2);
                        mma16816(ii, aih, bl + nt * 2);
                        mma16816(ii, ail, bh + nt * 2);
                        mma16816(mx, arh, bh + nt * 2);
                        mma16816(mx, arh, bl + nt * 2);
                        mma16816(mx, arl, bh + nt * 2);
                    }
                }
            }
        }
    }

    // ---- epilogue: Dr = RR - II + Cr ; Di = Mix + Ci ----
    const int tq = lane >> 2, tr = (lane & 3) * 2;
    #pragma unroll
    for (int nt8 = 0; nt8 < 4; ++nt8)
        #pragma unroll
        for (int h = 0; h < 2; ++h) {
            const int r  = bm + warp_m * 16 + h * 8 + tq;
            const int c0 = bn + warp_n * 32 + nt8 * 8 + tr;
            const long co = (long)r * Nn + c0;
            const float2 cr = *(const float2*)(C + co);
            const float2 ci = *(const float2*)(C + NN + co);
            const float vr0 = accRR[nt8][2*h]   - accII[nt8][2*h]   + cr.x;
            const float vr1 = accRR[nt8][2*h+1] - accII[nt8][2*h+1] + cr.y;
            const float vi0 = accMix[nt8][2*h]   + ci.x;
            const float vi1 = accMix[nt8][2*h+1] + ci.y;
            const long or_ = ((long)b * 2 + 0) * NN + co;
            const long oi_ = ((long)b * 2 + 1) * NN + co;
            if (isFinal) {
                *(float2*)(outF + or_) = make_float2(vr0, vr1);
                *(float2*)(outF + oi_) = make_float2(vi0, vi1);
            } else {
                __nv_bfloat16 h0, l0, h1, l1;
                bsplit(vr0, h0, l0); bsplit(vr1, h1, l1);
                __nv_bfloat162 hv; hv.x = h0; hv.y = h1;
                __nv_bfloat162 lv; lv.x = l0; lv.y = l1;
                *(__nv_bfloat162*)(outHi + or_) = hv;
                *(__nv_bfloat162*)(outLo + or_) = lv;
                bsplit(vi0, h0, l0); bsplit(vi1, h1, l1);
                hv.x = h0; hv.y = h1; lv.x = l0; lv.y = l1;
                *(__nv_bfloat162*)(outHi + oi_) = hv;
                *(__nv_bfloat162*)(outLo + oi_) = lv;
            }
        }
}

// ---------------------------------------------------------------------------
extern "C" void kernel_launch(void* const* d_in, const int* in_sizes, int n_in,
                              void* d_out, int out_size)
{
    const float* x      = (const float*)d_in[0];
    const float* coeffs = (const float*)d_in[1];
    if (n_in >= 2 && in_sizes[0] == 8 * 2 * NN) {
        const float* t = x; x = coeffs; coeffs = t;
    }

    __nv_bfloat16 *xtH, *xtL, *s0H, *s0L, *s1H, *s1L, *c7H, *c7L;
    cudaGetSymbolAddress((void**)&xtH, g_xt_hi);
    cudaGetSymbolAddress((void**)&xtL, g_xt_lo);
    cudaGetSymbolAddress((void**)&s0H, g_s0_hi);
    cudaGetSymbolAddress((void**)&s0L, g_s0_lo);
    cudaGetSymbolAddress((void**)&s1H, g_s1_hi);
    cudaGetSymbolAddress((void**)&s1L, g_s1_lo);
    cudaGetSymbolAddress((void**)&c7H, g_c7_hi);
    cudaGetSymbolAddress((void**)&c7L, g_c7_lo);

    cudaFuncSetAttribute(cgemm_mma, cudaFuncAttributeMaxDynamicSharedMemorySize, SMEM_BYTES);

    split_x_transpose<<<dim3(16, 16, 128), 256>>>(x, xtH, xtL);
    split_c7<<<(2 * NN + 255) / 256, 256>>>(coeffs + (long)7 * 2 * NN, c7H, c7L);

    dim3 grid(Nn / BN, Nn / BM, BATCH);   // (8, 8, 64)
    dim3 block(256);

    const __nv_bfloat16* aH = c7H;
    const __nv_bfloat16* aL = c7L;
    long aStride = 0;
    __nv_bfloat16* dstH[7] = {s0H, s1H, s0H, s1H, s0H, s1H, nullptr};
    __nv_bfloat16* dstL[7] = {s0L, s1L, s0L, s1L, s0L, s1L, nullptr};

    for (int t = 0; t < 7; ++t) {
        const float* Ct = coeffs + (long)(6 - t) * 2 * NN;
        const int fin = (t == 6);
        cgemm_mma<<<grid, block, SMEM_BYTES>>>(
            aH, aL, aStride, xtH, xtL, Ct,
            fin ? (float*)d_out : nullptr, dstH[t], dstL[t], fin);
        aH = dstH[t]; aL = dstL[t];
        aStride = 2L * NN;
    }
}

// round 6
// speedup vs baseline: 2.7863x; 1.0668x over previous
#include <cuda_runtime.h>
#include <cuda_bf16.h>
#include <cstdint>

#define Nn    512
#define NN    (Nn * Nn)
#define BATCH 64
#define KCH   32
#define NCHUNK (Nn / KCH)        // 16
#define BM 64
#define BN 64
#define MAT_B 8192               // 64 rows x 128B (hi|lo)
#define STG_B (4 * MAT_B)        // 32768: Ar, Ai, Xr, Xi
#define NSTG 3
#define SMEM_BYTES (NSTG * STG_B + 1024)

// ---------------- global scratch ----------------
__device__ __nv_bfloat16 g_xt_hi[(size_t)BATCH * 2 * NN];
__device__ __nv_bfloat16 g_xt_lo[(size_t)BATCH * 2 * NN];
__device__ __nv_bfloat16 g_s0_hi[(size_t)BATCH * 2 * NN];
__device__ __nv_bfloat16 g_s0_lo[(size_t)BATCH * 2 * NN];
__device__ __nv_bfloat16 g_s1_hi[(size_t)BATCH * 2 * NN];
__device__ __nv_bfloat16 g_s1_lo[(size_t)BATCH * 2 * NN];
__device__ __nv_bfloat16 g_c7_hi[(size_t)2 * NN];
__device__ __nv_bfloat16 g_c7_lo[(size_t)2 * NN];

// ---------------- helpers ----------------
__device__ __forceinline__ uint32_t smem_u32(const void* p) {
    uint32_t a;
    asm("{ .reg .u64 t; cvta.to.shared.u64 t, %1; cvt.u32.u64 %0, t; }" : "=r"(a) : "l"(p));
    return a;
}
#define CP_ASYNC16(dst, src) \
    asm volatile("cp.async.cg.shared.global [%0], [%1], 16;" :: "r"(dst), "l"(src))
#define CP_COMMIT()  asm volatile("cp.async.commit_group;" ::: "memory")
#define CP_WAIT1()   asm volatile("cp.async.wait_group 1;" ::: "memory")
#define CP_WAIT0()   asm volatile("cp.async.wait_group 0;" ::: "memory")

__device__ __forceinline__ void ldsm4(uint32_t* r, uint32_t addr) {
    asm volatile("ldmatrix.sync.aligned.m8n8.x4.shared.b16 {%0,%1,%2,%3}, [%4];"
                 : "=r"(r[0]), "=r"(r[1]), "=r"(r[2]), "=r"(r[3]) : "r"(addr));
}
__device__ __forceinline__ void mma16816(float* d, const uint32_t* a, const uint32_t* b) {
    asm volatile(
        "mma.sync.aligned.m16n8k16.row.col.f32.bf16.bf16.f32 "
        "{%0,%1,%2,%3}, {%4,%5,%6,%7}, {%8,%9}, {%0,%1,%2,%3};"
        : "+f"(d[0]), "+f"(d[1]), "+f"(d[2]), "+f"(d[3])
        : "r"(a[0]), "r"(a[1]), "r"(a[2]), "r"(a[3]), "r"(b[0]), "r"(b[1]));
}
__device__ __forceinline__ void bsplit(float v, __nv_bfloat16& h, __nv_bfloat16& l) {
    h = __float2bfloat16(v);
    l = __float2bfloat16(v - __bfloat162float(h));
}

// ---------------------------------------------------------------------------
__global__ void split_x_transpose(const float* __restrict__ x,
                                  __nv_bfloat16* __restrict__ xh,
                                  __nv_bfloat16* __restrict__ xl)
{
    __shared__ float t[32][33];
    const int z  = blockIdx.z;
    const int k0 = blockIdx.y * 32;
    const int n0 = blockIdx.x * 32;
    const int tx = threadIdx.x & 31, ty = threadIdx.x >> 5;
    const long zb = (long)z * NN;
    #pragma unroll
    for (int i = 0; i < 4; ++i)
        t[ty + 8 * i][tx] = x[zb + (long)(k0 + ty + 8 * i) * Nn + n0 + tx];
    __syncthreads();
    #pragma unroll
    for (int i = 0; i < 4; ++i) {
        const int n = n0 + ty + 8 * i, k = k0 + tx;
        __nv_bfloat16 h, l;
        bsplit(t[tx][ty + 8 * i], h, l);
        xh[zb + (long)n * Nn + k] = h;
        xl[zb + (long)n * Nn + k] = l;
    }
}

__global__ void split_c7(const float* __restrict__ c7,
                         __nv_bfloat16* __restrict__ h, __nv_bfloat16* __restrict__ l)
{
    const int i = blockIdx.x * 256 + threadIdx.x;
    if (i < 2 * NN) {
        __nv_bfloat16 hh, ll;
        bsplit(c7[i], hh, ll);
        h[i] = hh; l[i] = ll;
    }
}

// ---------------------------------------------------------------------------
// Fused complex GEMM, bf16x3 split, 2 accumulators (sign folded into Ai):
//   accD = Ar.Xr + (-Ai).Xi ; accM = Ar.Xi + Ai.Xr
//   Dr = accD + Cr ; Di = accM + Ci
// 64x64 tile, 256 threads, 2 CTAs/SM, 3-stage cp.async pipeline,
// per-CTA phase-staggered k-chunk order.
// ---------------------------------------------------------------------------
__global__ void __launch_bounds__(256, 2) cgemm_mma(
    const __nv_bfloat16* __restrict__ aHi, const __nv_bfloat16* __restrict__ aLo, long aStride,
    const __nv_bfloat16* __restrict__ xHi, const __nv_bfloat16* __restrict__ xLo,
    const float* __restrict__ C,
    float* __restrict__ outF,
    __nv_bfloat16* __restrict__ outHi, __nv_bfloat16* __restrict__ outLo,
    int isFinal)
{
    extern __shared__ char smraw[];
    const uint32_t sbase = (smem_u32(smraw) + 1023) & ~1023u;

    const int tid  = threadIdx.x;
    const int lane = tid & 31, wid = tid >> 5;
    const int warp_m = wid & 3;          // 4 m-tiles of 16 rows
    const int warp_n = wid >> 2;         // 2 n-tiles of 32 cols
    const int b  = blockIdx.z;
    const int bn = blockIdx.x * BN;
    const int bm = blockIdx.y * BM;

    // Per-CTA k-phase: decorrelate barrier timing of co-resident CTAs.
    const int phase =
        (int)(((blockIdx.x + blockIdx.y * 8u + blockIdx.z * 64u) * 11u) & 15u);

    // ---- cp.async per-thread constants: 8 x 16B per thread per chunk ----
    const int q = tid & 7, rowt = tid >> 3;         // q: 16B chunk in row, rowt: 0..31
    const __nv_bfloat16* srcs[8];
    uint32_t dsts[8];
    #pragma unroll
    for (int it = 0; it < 8; ++it) {
        const int mat = it >> 1, rhalf = it & 1;
        const int row = rowt + rhalf * 32;
        const bool isA = (mat < 2);
        const int comp = mat & 1;
        const __nv_bfloat16* hi = isA ? aHi : xHi;
        const __nv_bfloat16* lo = isA ? aLo : xLo;
        const long off = isA
            ? (long)b * aStride + (long)comp * NN + (long)(bm + row) * Nn
            : ((long)(2 * b) + comp) * NN + (long)(bn + row) * Nn;
        srcs[it] = (q < 4 ? hi : lo) + off + (q & 3) * 8;
        dsts[it] = (uint32_t)(mat * MAT_B) +
                   (((uint32_t)(row * 128 + q * 16)) ^ (uint32_t)((row & 7) << 4));
    }

    auto issue = [&](int c) {
        const uint32_t sd = sbase + (uint32_t)(c % NSTG) * STG_B;
        const long kadd = (long)(((c + phase) & (NCHUNK - 1)) * KCH);
        #pragma unroll
        for (int it = 0; it < 8; ++it)
            CP_ASYNC16(sd + dsts[it], srcs[it] + kadd);
        CP_COMMIT();
    };

    // ---- ldmatrix per-lane constants ----
    const uint32_t amask = (uint32_t)((lane & 7) << 4);
    const uint32_t abase = (uint32_t)((warp_m * 16 + (lane & 15)) * 128 + (lane >> 4) * 16);
    const uint32_t brow  = (uint32_t)((lane & 7) | ((lane >> 1) & 8));
    const uint32_t bcol  = (uint32_t)(((lane >> 3) & 1) * 16);

    float accD[4][4], accM[4][4];
    #pragma unroll
    for (int j = 0; j < 4; ++j)
        #pragma unroll
        for (int k = 0; k < 4; ++k) { accD[j][k] = 0.f; accM[j][k] = 0.f; }

    issue(0); issue(1);

    for (int c = 0; c < NCHUNK; ++c) {
        if (c < NCHUNK - 1) CP_WAIT1(); else CP_WAIT0();
        __syncthreads();

        const uint32_t st = sbase + (uint32_t)(c % NSTG) * STG_B;
        #pragma unroll
        for (int sl = 0; sl < 2; ++sl) {
            uint32_t arh[4], arl[4], aih[4], ail[4], nih[4], nil[4];
            const uint32_t rh = (abase + (uint32_t)sl * 32u) ^ amask;
            ldsm4(arh, st + rh);
            ldsm4(arl, st + (rh ^ 64u));
            ldsm4(aih, st + MAT_B + rh);
            ldsm4(ail, st + MAT_B + (rh ^ 64u));
            #pragma unroll
            for (int j = 0; j < 4; ++j) {
                nih[j] = aih[j] ^ 0x80008000u;
                nil[j] = ail[j] ^ 0x80008000u;
            }

            #pragma unroll
            for (int ng = 0; ng < 2; ++ng) {
                const uint32_t bb =
                    ((uint32_t)((warp_n * 32 + ng * 16 + brow) * 128) + bcol
                     + (uint32_t)sl * 32u) ^ amask;
                {   // B = Xr: accD += Ar.Xr ; accM += Ai.Xr
                    uint32_t bh[4], bl[4];
                    ldsm4(bh, st + 2u * MAT_B + bb);
                    ldsm4(bl, st + 2u * MAT_B + (bb ^ 64u));
                    #pragma unroll
                    for (int nt = 0; nt < 2; ++nt) {
                        float* dd = accD[ng * 2 + nt];
                        float* mm = accM[ng * 2 + nt];
                        mma16816(dd, arh, bh + nt * 2);
                        mma16816(dd, arh, bl + nt * 2);
                        mma16816(dd, arl, bh + nt * 2);
                        mma16816(mm, aih, bh + nt * 2);
                        mma16816(mm, aih, bl + nt * 2);
                        mma16816(mm, ail, bh + nt * 2);
                    }
                }
                {   // B = Xi: accD += (-Ai).Xi ; accM += Ar.Xi
                    uint32_t bh[4], bl[4];
                    ldsm4(bh, st + 3u * MAT_B + bb);
                    ldsm4(bl, st + 3u * MAT_B + (bb ^ 64u));
                    #pragma unroll
                    for (int nt = 0; nt < 2; ++nt) {
                        float* dd = accD[ng * 2 + nt];
                        float* mm = accM[ng * 2 + nt];
                        mma16816(dd, nih, bh + nt * 2);
                        mma16816(dd, nih, bl + nt * 2);
                        mma16816(dd, nil, bh + nt * 2);
                        mma16816(mm, arh, bh + nt * 2);
                        mma16816(mm, arh, bl + nt * 2);
                        mma16816(mm, arl, bh + nt * 2);
                    }
                }
            }
            // Launch next chunk's loads after the first slice's ldsm burst:
            // keeps the post-barrier tensor ramp free of LSU issue traffic.
            if (sl == 0 && c + 2 < NCHUNK) issue(c + 2);
        }
    }

    // ---- epilogue: Dr = accD + Cr ; Di = accM + Ci ----
    const int tq = lane >> 2, tr = (lane & 3) * 2;
    #pragma unroll
    for (int nt8 = 0; nt8 < 4; ++nt8)
        #pragma unroll
        for (int h = 0; h < 2; ++h) {
            const int r  = bm + warp_m * 16 + h * 8 + tq;
            const int c0 = bn + warp_n * 32 + nt8 * 8 + tr;
            const long co = (long)r * Nn + c0;
            const float2 cr = *(const float2*)(C + co);
            const float2 ci = *(const float2*)(C + NN + co);
            const float vr0 = accD[nt8][2*h]   + cr.x;
            const float vr1 = accD[nt8][2*h+1] + cr.y;
            const float vi0 = accM[nt8][2*h]   + ci.x;
            const float vi1 = accM[nt8][2*h+1] + ci.y;
            const long or_ = ((long)b * 2 + 0) * NN + co;
            const long oi_ = ((long)b * 2 + 1) * NN + co;
            if (isFinal) {
                *(float2*)(outF + or_) = make_float2(vr0, vr1);
                *(float2*)(outF + oi_) = make_float2(vi0, vi1);
            } else {
                __nv_bfloat16 h0, l0, h1, l1;
                bsplit(vr0, h0, l0); bsplit(vr1, h1, l1);
                __nv_bfloat162 hv; hv.x = h0; hv.y = h1;
                __nv_bfloat162 lv; lv.x = l0; lv.y = l1;
                *(__nv_bfloat162*)(outHi + or_) = hv;
                *(__nv_bfloat162*)(outLo + or_) = lv;
                bsplit(vi0, h0, l0); bsplit(vi1, h1, l1);
                hv.x = h0; hv.y = h1; lv.x = l0; lv.y = l1;
                *(__nv_bfloat162*)(outHi + oi_) = hv;
                *(__nv_bfloat162*)(outLo + oi_) = lv;
            }
        }
}

// ---------------------------------------------------------------------------
extern "C" void kernel_launch(void* const* d_in, const int* in_sizes, int n_in,
                              void* d_out, int out_size)
{
    const float* x      = (const float*)d_in[0];
    const float* coeffs = (const float*)d_in[1];
    if (n_in >= 2 && in_sizes[0] == 8 * 2 * NN) {
        const float* t = x; x = coeffs; coeffs = t;
    }

    __nv_bfloat16 *xtH, *xtL, *s0H, *s0L, *s1H, *s1L, *c7H, *c7L;
    cudaGetSymbolAddress((void**)&xtH, g_xt_hi);
    cudaGetSymbolAddress((void**)&xtL, g_xt_lo);
    cudaGetSymbolAddress((void**)&s0H, g_s0_hi);
    cudaGetSymbolAddress((void**)&s0L, g_s0_lo);
    cudaGetSymbolAddress((void**)&s1H, g_s1_hi);
    cudaGetSymbolAddress((void**)&s1L, g_s1_lo);
    cudaGetSymbolAddress((void**)&c7H, g_c7_hi);
    cudaGetSymbolAddress((void**)&c7L, g_c7_lo);

    cudaFuncSetAttribute(cgemm_mma, cudaFuncAttributeMaxDynamicSharedMemorySize, SMEM_BYTES);

    split_x_transpose<<<dim3(16, 16, 128), 256>>>(x, xtH, xtL);
    split_c7<<<(2 * NN + 255) / 256, 256>>>(coeffs + (long)7 * 2 * NN, c7H, c7L);

    dim3 grid(Nn / BN, Nn / BM, BATCH);   // (8, 8, 64)
    dim3 block(256);

    const __nv_bfloat16* aH = c7H;
    const __nv_bfloat16* aL = c7L;
    long aStride = 0;
    __nv_bfloat16* dstH[7] = {s0H, s1H, s0H, s1H, s0H, s1H, nullptr};
    __nv_bfloat16* dstL[7] = {s0L, s1L, s0L, s1L, s0L, s1L, nullptr};

    for (int t = 0; t < 7; ++t) {
        const float* Ct = coeffs + (long)(6 - t) * 2 * NN;
        const int fin = (t == 6);
        cgemm_mma<<<grid, block, SMEM_BYTES>>>(
            aH, aL, aStride, xtH, xtL, Ct,
            fin ? (float*)d_out : nullptr, dstH[t], dstL[t], fin);
        aH = dstH[t]; aL = dstL[t];
        aStride = 2L * NN;
    }
}

// round 7
// speedup vs baseline: 3.7528x; 1.3469x over previous
#include <cuda_runtime.h>
#include <cuda_fp16.h>
#include <cstdint>

#define Nn    512
#define NN    (Nn * Nn)
#define BATCH 64
#define KCH   32
#define NCHUNK (Nn / KCH)        // 16
#define BM 64
#define BN 64
#define MAT_B 8192               // 64 rows x 128B
#define STG_B (3 * MAT_B)        // 24576: Ar[hi|lo], Ai[hi|lo], X[XrH|XiH]
#define NSTG 4
#define SMEM_BYTES (NSTG * STG_B + 1024)

// ---------------- global scratch ----------------
__device__ __half g_xt_h[(size_t)BATCH * 2 * NN];   // X^T, single fp16
__device__ __half g_s0_h[(size_t)BATCH * 2 * NN];   // S ping-pong, fp16 pair
__device__ __half g_s0_l[(size_t)BATCH * 2 * NN];
__device__ __half g_s1_h[(size_t)BATCH * 2 * NN];
__device__ __half g_s1_l[(size_t)BATCH * 2 * NN];
__device__ __half g_c7_h[(size_t)2 * NN];
__device__ __half g_c7_l[(size_t)2 * NN];

// ---------------- helpers ----------------
__device__ __forceinline__ uint32_t smem_u32(const void* p) {
    uint32_t a;
    asm("{ .reg .u64 t; cvta.to.shared.u64 t, %1; cvt.u32.u64 %0, t; }" : "=r"(a) : "l"(p));
    return a;
}
#define CP_ASYNC16(dst, src) \
    asm volatile("cp.async.cg.shared.global [%0], [%1], 16;" :: "r"(dst), "l"(src))
#define CP_COMMIT()  asm volatile("cp.async.commit_group;" ::: "memory")
#define CP_WAIT2()   asm volatile("cp.async.wait_group 2;" ::: "memory")
#define CP_WAIT1()   asm volatile("cp.async.wait_group 1;" ::: "memory")
#define CP_WAIT0()   asm volatile("cp.async.wait_group 0;" ::: "memory")

__device__ __forceinline__ void ldsm4(uint32_t* r, uint32_t addr) {
    asm volatile("ldmatrix.sync.aligned.m8n8.x4.shared.b16 {%0,%1,%2,%3}, [%4];"
                 : "=r"(r[0]), "=r"(r[1]), "=r"(r[2]), "=r"(r[3]) : "r"(addr));
}
__device__ __forceinline__ void mma16816(float* d, const uint32_t* a, const uint32_t* b) {
    asm volatile(
        "mma.sync.aligned.m16n8k16.row.col.f32.f16.f16.f32 "
        "{%0,%1,%2,%3}, {%4,%5,%6,%7}, {%8,%9}, {%0,%1,%2,%3};"
        : "+f"(d[0]), "+f"(d[1]), "+f"(d[2]), "+f"(d[3])
        : "r"(a[0]), "r"(a[1]), "r"(a[2]), "r"(a[3]), "r"(b[0]), "r"(b[1]));
}
__device__ __forceinline__ void hsplit(float v, __half& h, __half& l) {
    h = __float2half_rn(v);
    l = __float2half_rn(v - __half2float(h));
}

// ---------------------------------------------------------------------------
// Precompute: transpose X, single fp16:  xt[b*2+c][n][k] = fp16(x[b][c][k][n])
// ---------------------------------------------------------------------------
__global__ void x_transpose_h(const float* __restrict__ x,
                              __half* __restrict__ xh)
{
    __shared__ float t[32][33];
    const int z  = blockIdx.z;
    const int k0 = blockIdx.y * 32;
    const int n0 = blockIdx.x * 32;
    const int tx = threadIdx.x & 31, ty = threadIdx.x >> 5;
    const long zb = (long)z * NN;
    #pragma unroll
    for (int i = 0; i < 4; ++i)
        t[ty + 8 * i][tx] = x[zb + (long)(k0 + ty + 8 * i) * Nn + n0 + tx];
    __syncthreads();
    #pragma unroll
    for (int i = 0; i < 4; ++i) {
        const int n = n0 + ty + 8 * i, k = k0 + tx;
        xh[zb + (long)n * Nn + k] = __float2half_rn(t[tx][ty + 8 * i]);
    }
}

__global__ void split_c7(const float* __restrict__ c7,
                         __half* __restrict__ h, __half* __restrict__ l)
{
    const int i = blockIdx.x * 256 + threadIdx.x;
    if (i < 2 * NN) {
        __half hh, ll;
        hsplit(c7[i], hh, ll);
        h[i] = hh; l[i] = ll;
    }
}

// ---------------------------------------------------------------------------
// Fused complex GEMM, fp16 2-pass split (A exact pair, X hi-only):
//   accD = (Arh+Arl).XrH + (-(Aih+Ail)).XiH ; accM = (Aih+Ail).XrH + (Arh+Arl).XiH
//   Dr = accD + Cr ; Di = accM + Ci
// 64x64 tile, 256 threads, 2 CTAs/SM, 4-stage cp.async pipeline,
// per-CTA phase-staggered k-chunk order.
// smem per stage: Ar rows [hi|lo] 8KB, Ai rows [hi|lo] 8KB, X rows [XrH|XiH] 8KB.
// ---------------------------------------------------------------------------
__global__ void __launch_bounds__(256, 2) cgemm_mma(
    const __half* __restrict__ aHi, const __half* __restrict__ aLo, long aStride,
    const __half* __restrict__ xH,
    const float* __restrict__ C,
    float* __restrict__ outF,
    __half* __restrict__ outHi, __half* __restrict__ outLo,
    int isFinal)
{
    extern __shared__ char smraw[];
    const uint32_t sbase = (smem_u32(smraw) + 1023) & ~1023u;

    const int tid  = threadIdx.x;
    const int lane = tid & 31, wid = tid >> 5;
    const int warp_m = wid & 3;          // 4 m-tiles of 16 rows
    const int warp_n = wid >> 2;         // 2 n-tiles of 32 cols
    const int b  = blockIdx.z;
    const int bn = blockIdx.x * BN;
    const int bm = blockIdx.y * BM;

    // Per-CTA k-phase: decorrelate barrier timing of co-resident CTAs.
    const int phase =
        (int)(((blockIdx.x + blockIdx.y * 8u + blockIdx.z * 64u) * 11u) & 15u);

    // ---- cp.async per-thread constants: 6 x 16B per thread per chunk ----
    const int q = tid & 7, rowt = tid >> 3;   // q: 16B chunk in row, rowt: 0..31
    const __half* srcs[6];
    uint32_t dsts[6];
    #pragma unroll
    for (int it = 0; it < 6; ++it) {
        const int rhalf = it & 1;
        const int row = rowt + rhalf * 32;
        long off;
        const __half* base;
        uint32_t matbase;
        if (it < 4) {                       // A mats: 0,1 -> Ar ; 2,3 -> Ai
            const int comp = it >> 1;
            base = (q < 4) ? aHi : aLo;     // [hi 64B | lo 64B] per row
            off  = (long)b * aStride + (long)comp * NN + (long)(bm + row) * Nn;
            matbase = (uint32_t)(comp * MAT_B);
        } else {                            // X mat: [XrH 64B | XiH 64B] per row
            const int comp = (q < 4) ? 0 : 1;
            base = xH;
            off  = ((long)(2 * b) + comp) * NN + (long)(bn + row) * Nn;
            matbase = 2u * MAT_B;
        }
        srcs[it] = base + off + (q & 3) * 8;
        dsts[it] = matbase +
                   (((uint32_t)(row * 128 + q * 16)) ^ (uint32_t)((row & 7) << 4));
    }

    auto issue = [&](int c) {
        const uint32_t sd = sbase + (uint32_t)(c % NSTG) * STG_B;
        const long kadd = (long)(((c + phase) & (NCHUNK - 1)) * KCH);
        #pragma unroll
        for (int it = 0; it < 6; ++it)
            CP_ASYNC16(sd + dsts[it], srcs[it] + kadd);
        CP_COMMIT();
    };

    // ---- ldmatrix per-lane constants ----
    const uint32_t amask = (uint32_t)((lane & 7) << 4);
    const uint32_t abase = (uint32_t)((warp_m * 16 + (lane & 15)) * 128 + (lane >> 4) * 16);
    const uint32_t brow  = (uint32_t)((lane & 7) | ((lane >> 1) & 8));
    const uint32_t bcol  = (uint32_t)(((lane >> 3) & 1) * 16);

    float accD[4][4], accM[4][4];
    #pragma unroll
    for (int j = 0; j < 4; ++j)
        #pragma unroll
        for (int k = 0; k < 4; ++k) { accD[j][k] = 0.f; accM[j][k] = 0.f; }

    issue(0); issue(1); issue(2);

    for (int c = 0; c < NCHUNK; ++c) {
        if (c < NCHUNK - 2)       CP_WAIT2();
        else if (c == NCHUNK - 2) CP_WAIT1();
        else                      CP_WAIT0();
        __syncthreads();

        const uint32_t st = sbase + (uint32_t)(c % NSTG) * STG_B;
        #pragma unroll
        for (int sl = 0; sl < 2; ++sl) {
            uint32_t arh[4], arl[4], aih[4], ail[4], nih[4], nil[4];
            const uint32_t rh = (abase + (uint32_t)sl * 32u) ^ amask;
            ldsm4(arh, st + rh);
            ldsm4(arl, st + (rh ^ 64u));
            ldsm4(aih, st + MAT_B + rh);
            ldsm4(ail, st + MAT_B + (rh ^ 64u));
            #pragma unroll
            for (int j = 0; j < 4; ++j) {
                nih[j] = aih[j] ^ 0x80008000u;
                nil[j] = ail[j] ^ 0x80008000u;
            }

            #pragma unroll
            for (int ng = 0; ng < 2; ++ng) {
                const uint32_t bb =
                    ((uint32_t)((warp_n * 32 + ng * 16 + brow) * 128) + bcol
                     + (uint32_t)sl * 32u) ^ amask;
                uint32_t brh[4], bih[4];
                ldsm4(brh, st + 2u * MAT_B + bb);           // XrH
                ldsm4(bih, st + 2u * MAT_B + (bb ^ 64u));   // XiH
                #pragma unroll
                for (int nt = 0; nt < 2; ++nt) {
                    float* dd = accD[ng * 2 + nt];
                    float* mm = accM[ng * 2 + nt];
                    // accD += Ar.Xr - Ai.Xi   (A exact: hi+lo passes)
                    mma16816(dd, arh, brh + nt * 2);
                    mma16816(dd, arl, brh + nt * 2);
                    mma16816(dd, nih, bih + nt * 2);
                    mma16816(dd, nil, bih + nt * 2);
                    // accM += Ai.Xr + Ar.Xi
                    mma16816(mm, aih, brh + nt * 2);
                    mma16816(mm, ail, brh + nt * 2);
                    mma16816(mm, arh, bih + nt * 2);
                    mma16816(mm, arl, bih + nt * 2);
                }
            }
            // Launch next chunk's loads after the first slice's ldsm burst.
            if (sl == 0 && c + 3 < NCHUNK) issue(c + 3);
        }
    }

    // ---- epilogue: Dr = accD + Cr ; Di = accM + Ci ----
    const int tq = lane >> 2, tr = (lane & 3) * 2;
    #pragma unroll
    for (int nt8 = 0; nt8 < 4; ++nt8)
        #pragma unroll
        for (int h = 0; h < 2; ++h) {
            const int r  = bm + warp_m * 16 + h * 8 + tq;
            const int c0 = bn + warp_n * 32 + nt8 * 8 + tr;
            const long co = (long)r * Nn + c0;
            const float2 cr = *(const float2*)(C + co);
            const float2 ci = *(const float2*)(C + NN + co);
            const float vr0 = accD[nt8][2*h]   + cr.x;
            const float vr1 = accD[nt8][2*h+1] + cr.y;
            const float vi0 = accM[nt8][2*h]   + ci.x;
            const float vi1 = accM[nt8][2*h+1] + ci.y;
            const long or_ = ((long)b * 2 + 0) * NN + co;
            const long oi_ = ((long)b * 2 + 1) * NN + co;
            if (isFinal) {
                *(float2*)(outF + or_) = make_float2(vr0, vr1);
                *(float2*)(outF + oi_) = make_float2(vi0, vi1);
            } else {
                __half h0, l0, h1, l1;
                hsplit(vr0, h0, l0); hsplit(vr1, h1, l1);
                __half2 hv; hv.x = h0; hv.y = h1;
                __half2 lv; lv.x = l0; lv.y = l1;
                *(__half2*)(outHi + or_) = hv;
                *(__half2*)(outLo + or_) = lv;
                hsplit(vi0, h0, l0); hsplit(vi1, h1, l1);
                hv.x = h0; hv.y = h1; lv.x = l0; lv.y = l1;
                *(__half2*)(outHi + oi_) = hv;
                *(__half2*)(outLo + oi_) = lv;
            }
        }
}

// ---------------------------------------------------------------------------
extern "C" void kernel_launch(void* const* d_in, const int* in_sizes, int n_in,
                              void* d_out, int out_size)
{
    const float* x      = (const float*)d_in[0];
    const float* coeffs = (const float*)d_in[1];
    if (n_in >= 2 && in_sizes[0] == 8 * 2 * NN) {
        const float* t = x; x = coeffs; coeffs = t;
    }

    __half *xtH, *s0H, *s0L, *s1H, *s1L, *c7H, *c7L;
    cudaGetSymbolAddress((void**)&xtH, g_xt_h);
    cudaGetSymbolAddress((void**)&s0H, g_s0_h);
    cudaGetSymbolAddress((void**)&s0L, g_s0_l);
    cudaGetSymbolAddress((void**)&s1H, g_s1_h);
    cudaGetSymbolAddress((void**)&s1L, g_s1_l);
    cudaGetSymbolAddress((void**)&c7H, g_c7_h);
    cudaGetSymbolAddress((void**)&c7L, g_c7_l);

    cudaFuncSetAttribute(cgemm_mma, cudaFuncAttributeMaxDynamicSharedMemorySize, SMEM_BYTES);

    x_transpose_h<<<dim3(16, 16, 128), 256>>>(x, xtH);
    split_c7<<<(2 * NN + 255) / 256, 256>>>(coeffs + (long)7 * 2 * NN, c7H, c7L);

    dim3 grid(Nn / BN, Nn / BM, BATCH);   // (8, 8, 64)
    dim3 block(256);

    const __half* aH = c7H;
    const __half* aL = c7L;
    long aStride = 0;
    __half* dstH[7] = {s0H, s1H, s0H, s1H, s0H, s1H, nullptr};
    __half* dstL[7] = {s0L, s1L, s0L, s1L, s0L, s1L, nullptr};

    for (int t = 0; t < 7; ++t) {
        const float* Ct = coeffs + (long)(6 - t) * 2 * NN;
        const int fin = (t == 6);
        cgemm_mma<<<grid, block, SMEM_BYTES>>>(
            aH, aL, aStride, xtH, Ct,
            fin ? (float*)d_out : nullptr, dstH[t], dstL[t], fin);
        aH = dstH[t]; aL = dstL[t];
        aStride = 2L * NN;
    }
}

// round 8
// speedup vs baseline: 6.7491x; 1.7984x over previous
#include <cuda_runtime.h>
#include <cuda_fp16.h>
#include <cstdint>

#define Nn    512
#define NN    (Nn * Nn)
#define BATCH 64
#define KCH   32
#define NCHUNK (Nn / KCH)        // 16
#define BM 128
#define BN 64
#define MAT_A 16384              // 128 rows x 128B [ArH k32 | AiH k32]
#define MAT_X 8192               // 64 rows x 128B [XrH k32 | XiH k32]
#define STG_B (MAT_A + MAT_X)    // 24576
#define NSTG 4
#define SMEM_BYTES (NSTG * STG_B + 1024)

// ---------------- global scratch ----------------
__device__ __half g_xt_h[(size_t)BATCH * 2 * NN];   // X^T single fp16
__device__ __half g_s0_h[(size_t)BATCH * 2 * NN];   // S ping-pong, single fp16
__device__ __half g_s1_h[(size_t)BATCH * 2 * NN];
__device__ __half g_c7_h[(size_t)2 * NN];

// ---------------- helpers ----------------
__device__ __forceinline__ uint32_t smem_u32(const void* p) {
    uint32_t a;
    asm("{ .reg .u64 t; cvta.to.shared.u64 t, %1; cvt.u32.u64 %0, t; }" : "=r"(a) : "l"(p));
    return a;
}
#define CP_ASYNC16(dst, src) \
    asm volatile("cp.async.cg.shared.global [%0], [%1], 16;" :: "r"(dst), "l"(src))
#define CP_COMMIT()  asm volatile("cp.async.commit_group;" ::: "memory")
#define CP_WAIT2()   asm volatile("cp.async.wait_group 2;" ::: "memory")
#define CP_WAIT1()   asm volatile("cp.async.wait_group 1;" ::: "memory")
#define CP_WAIT0()   asm volatile("cp.async.wait_group 0;" ::: "memory")

__device__ __forceinline__ void ldsm4(uint32_t* r, uint32_t addr) {
    asm volatile("ldmatrix.sync.aligned.m8n8.x4.shared.b16 {%0,%1,%2,%3}, [%4];"
                 : "=r"(r[0]), "=r"(r[1]), "=r"(r[2]), "=r"(r[3]) : "r"(addr));
}
__device__ __forceinline__ void mma16816(float* d, const uint32_t* a, const uint32_t* b) {
    asm volatile(
        "mma.sync.aligned.m16n8k16.row.col.f32.f16.f16.f32 "
        "{%0,%1,%2,%3}, {%4,%5,%6,%7}, {%8,%9}, {%0,%1,%2,%3};"
        : "+f"(d[0]), "+f"(d[1]), "+f"(d[2]), "+f"(d[3])
        : "r"(a[0]), "r"(a[1]), "r"(a[2]), "r"(a[3]), "r"(b[0]), "r"(b[1]));
}

// ---------------------------------------------------------------------------
// Precompute: transpose X, single fp16
// ---------------------------------------------------------------------------
__global__ void x_transpose_h(const float* __restrict__ x,
                              __half* __restrict__ xh)
{
    __shared__ float t[32][33];
    const int z  = blockIdx.z;
    const int k0 = blockIdx.y * 32;
    const int n0 = blockIdx.x * 32;
    const int tx = threadIdx.x & 31, ty = threadIdx.x >> 5;
    const long zb = (long)z * NN;
    #pragma unroll
    for (int i = 0; i < 4; ++i)
        t[ty + 8 * i][tx] = x[zb + (long)(k0 + ty + 8 * i) * Nn + n0 + tx];
    __syncthreads();
    #pragma unroll
    for (int i = 0; i < 4; ++i) {
        const int n = n0 + ty + 8 * i, k = k0 + tx;
        xh[zb + (long)n * Nn + k] = __float2half_rn(t[tx][ty + 8 * i]);
    }
}

__global__ void conv_c7(const float* __restrict__ c7, __half* __restrict__ h)
{
    const int i = blockIdx.x * 256 + threadIdx.x;
    if (i < 2 * NN) h[i] = __float2half_rn(c7[i]);
}

// ---------------------------------------------------------------------------
// Fused complex GEMM, single-fp16 operands (4 passes):
//   accD = Ar.Xr + (-Ai).Xi ; accM = Ai.Xr + Ar.Xi
//   Dr = accD + Cr ; Di = accM + Ci
// CTA 128x64, 8 warps (4m x 2n), warp tile 32x32, 2 CTAs/SM,
// 4-stage cp.async pipeline, phase-staggered k order.
// smem rows pack components: A row = [ArH | AiH], X row = [XrH | XiH].
// ---------------------------------------------------------------------------
__global__ void __launch_bounds__(256, 2) cgemm_mma(
    const __half* __restrict__ aH, long aStride,
    const __half* __restrict__ xH,
    const float* __restrict__ C,
    float* __restrict__ outF,
    __half* __restrict__ outH,
    int isFinal)
{
    extern __shared__ char smraw[];
    const uint32_t sbase = (smem_u32(smraw) + 1023) & ~1023u;

    const int tid  = threadIdx.x;
    const int lane = tid & 31, wid = tid >> 5;
    const int warp_m = wid & 3;          // 4 m-tiles of 32 rows
    const int warp_n = wid >> 2;         // 2 n-tiles of 32 cols
    const int b  = blockIdx.z;
    const int bn = blockIdx.x * BN;
    const int bm = blockIdx.y * BM;

    // Per-CTA k-phase: decorrelate barrier timing of co-resident CTAs.
    const int phase =
        (int)(((blockIdx.x + blockIdx.y * 8u + blockIdx.z * 32u) * 11u) & 15u);

    // ---- cp.async per-thread constants: 6 x 16B per thread per chunk ----
    const int q = tid & 7, rowt = tid >> 3;   // q: 16B chunk in 128B row, rowt: 0..31
    const int comp = (q >= 4);
    const __half* srcs[6];
    uint32_t dsts[6];
    #pragma unroll
    for (int it = 0; it < 6; ++it) {
        if (it < 4) {                          // A: rows rowt + it*32 (0..127)
            const int row = rowt + it * 32;
            srcs[it] = aH + (long)b * aStride + (long)comp * NN
                     + (long)(bm + row) * Nn + (q & 3) * 8;
            dsts[it] = ((uint32_t)(row * 128 + q * 16)) ^ (uint32_t)((row & 7) << 4);
        } else {                               // X: rows rowt + (it-4)*32 (0..63)
            const int row = rowt + (it - 4) * 32;
            srcs[it] = xH + ((long)(2 * b) + comp) * NN
                     + (long)(bn + row) * Nn + (q & 3) * 8;
            dsts[it] = (uint32_t)MAT_A +
                       (((uint32_t)(row * 128 + q * 16)) ^ (uint32_t)((row & 7) << 4));
        }
    }

    auto issue = [&](int c) {
        const uint32_t sd = sbase + (uint32_t)(c % NSTG) * STG_B;
        const long kadd = (long)(((c + phase) & (NCHUNK - 1)) * KCH);
        #pragma unroll
        for (int it = 0; it < 6; ++it)
            CP_ASYNC16(sd + dsts[it], srcs[it] + kadd);
        CP_COMMIT();
    };

    // ---- ldmatrix per-lane constants ----
    const uint32_t amask = (uint32_t)((lane & 7) << 4);
    const uint32_t abase = (uint32_t)((warp_m * 32 + (lane & 15)) * 128 + (lane >> 4) * 16);
    const uint32_t brow  = (uint32_t)((lane & 7) | ((lane >> 1) & 8));
    const uint32_t bcol  = (uint32_t)(((lane >> 3) & 1) * 16);

    float accD[2][4][4], accM[2][4][4];
    #pragma unroll
    for (int i = 0; i < 2; ++i)
        #pragma unroll
        for (int j = 0; j < 4; ++j)
            #pragma unroll
            for (int k = 0; k < 4; ++k) { accD[i][j][k] = 0.f; accM[i][j][k] = 0.f; }

    issue(0); issue(1); issue(2);

    for (int c = 0; c < NCHUNK; ++c) {
        if (c < NCHUNK - 2)       CP_WAIT2();
        else if (c == NCHUNK - 2) CP_WAIT1();
        else                      CP_WAIT0();
        __syncthreads();

        const uint32_t st = sbase + (uint32_t)(c % NSTG) * STG_B;
        #pragma unroll
        for (int sl = 0; sl < 2; ++sl) {
            uint32_t ar[2][4], ai[2][4], an[2][4];
            #pragma unroll
            for (int mt = 0; mt < 2; ++mt) {
                const uint32_t rh =
                    (abase + (uint32_t)mt * 2048u + (uint32_t)sl * 32u) ^ amask;
                ldsm4(ar[mt], st + rh);             // Ar half
                ldsm4(ai[mt], st + (rh ^ 64u));     // Ai half
                #pragma unroll
                for (int j = 0; j < 4; ++j) an[mt][j] = ai[mt][j] ^ 0x80008000u;
            }

            #pragma unroll
            for (int ng = 0; ng < 2; ++ng) {
                const uint32_t bb =
                    ((uint32_t)((warp_n * 32 + ng * 16 + brow) * 128) + bcol
                     + (uint32_t)sl * 32u) ^ amask;
                uint32_t br[4], bi[4];
                ldsm4(br, st + (uint32_t)MAT_A + bb);            // Xr half
                ldsm4(bi, st + (uint32_t)MAT_A + (bb ^ 64u));    // Xi half
                #pragma unroll
                for (int mt = 0; mt < 2; ++mt)
                    #pragma unroll
                    for (int nt = 0; nt < 2; ++nt) {
                        float* dd = accD[mt][ng * 2 + nt];
                        float* mm = accM[mt][ng * 2 + nt];
                        mma16816(dd, ar[mt], br + nt * 2);
                        mma16816(dd, an[mt], bi + nt * 2);
                        mma16816(mm, ai[mt], br + nt * 2);
                        mma16816(mm, ar[mt], bi + nt * 2);
                    }
            }
            // Launch next chunk's loads after the first slice's ldsm burst.
            if (sl == 0 && c + 3 < NCHUNK) issue(c + 3);
        }
    }

    // ---- epilogue: Dr = accD + Cr ; Di = accM + Ci ----
    const int tq = lane >> 2, tr = (lane & 3) * 2;
    #pragma unroll
    for (int mt = 0; mt < 2; ++mt)
        #pragma unroll
        for (int j = 0; j < 4; ++j)
            #pragma unroll
            for (int h = 0; h < 2; ++h) {
                const int r  = bm + warp_m * 32 + mt * 16 + h * 8 + tq;
                const int c0 = bn + warp_n * 32 + j * 8 + tr;
                const long co = (long)r * Nn + c0;
                const float2 cr = *(const float2*)(C + co);
                const float2 ci = *(const float2*)(C + NN + co);
                const float vr0 = accD[mt][j][2*h]   + cr.x;
                const float vr1 = accD[mt][j][2*h+1] + cr.y;
                const float vi0 = accM[mt][j][2*h]   + ci.x;
                const float vi1 = accM[mt][j][2*h+1] + ci.y;
                const long or_ = ((long)b * 2 + 0) * NN + co;
                const long oi_ = ((long)b * 2 + 1) * NN + co;
                if (isFinal) {
                    *(float2*)(outF + or_) = make_float2(vr0, vr1);
                    *(float2*)(outF + oi_) = make_float2(vi0, vi1);
                } else {
                    __half2 hv;
                    hv.x = __float2half_rn(vr0); hv.y = __float2half_rn(vr1);
                    *(__half2*)(outH + or_) = hv;
                    hv.x = __float2half_rn(vi0); hv.y = __float2half_rn(vi1);
                    *(__half2*)(outH + oi_) = hv;
                }
            }
}

// ---------------------------------------------------------------------------
extern "C" void kernel_launch(void* const* d_in, const int* in_sizes, int n_in,
                              void* d_out, int out_size)
{
    const float* x      = (const float*)d_in[0];
    const float* coeffs = (const float*)d_in[1];
    if (n_in >= 2 && in_sizes[0] == 8 * 2 * NN) {
        const float* t = x; x = coeffs; coeffs = t;
    }

    __half *xtH, *s0H, *s1H, *c7H;
    cudaGetSymbolAddress((void**)&xtH, g_xt_h);
    cudaGetSymbolAddress((void**)&s0H, g_s0_h);
    cudaGetSymbolAddress((void**)&s1H, g_s1_h);
    cudaGetSymbolAddress((void**)&c7H, g_c7_h);

    cudaFuncSetAttribute(cgemm_mma, cudaFuncAttributeMaxDynamicSharedMemorySize, SMEM_BYTES);

    x_transpose_h<<<dim3(16, 16, 128), 256>>>(x, xtH);
    conv_c7<<<(2 * NN + 255) / 256, 256>>>(coeffs + (long)7 * 2 * NN, c7H);

    dim3 grid(Nn / BN, Nn / BM, BATCH);   // (8, 4, 64)
    dim3 block(256);

    const __half* aP = c7H;
    long aStride = 0;
    __half* dstH[7] = {s0H, s1H, s0H, s1H, s0H, s1H, nullptr};

    for (int t = 0; t < 7; ++t) {
        const float* Ct = coeffs + (long)(6 - t) * 2 * NN;
        const int fin = (t == 6);
        cgemm_mma<<<grid, block, SMEM_BYTES>>>(
            aP, aStride, xtH, Ct,
            fin ? (float*)d_out : nullptr, dstH[t], fin);
        aP = dstH[t];
        aStride = 2L * NN;
    }
}